// round 7
// baseline (speedup 1.0000x reference)
#include <cuda_runtime.h>
#include <math.h>

// Problem dims
#define H   256
#define H2  512
#define H3  768
#define B   64
#define L   2048
#define V   32000
#define NCH 32              // kA: l-chunks of 64
#define NB7 500             // k7 blocks (V/64)

typedef unsigned long long ull;

// ---------------- scratch (device globals) ----------------------------------------
__device__ __align__(16) float g_w2p[8][H2];
__device__ __align__(16) float g_w2[H2];
__device__ float g_bias;
__device__ __align__(16) float g_ehb[B];
__device__ __align__(16) float g_attn[B * L];
__device__ __align__(16) float g_pm[B * NCH];
__device__ __align__(16) float g_ps[B * NCH];
__device__ __align__(16) float g_ctxp[B * NCH * H];
__device__ __align__(16) float g_xT[H2 * B];         // [emb; ctx] transposed [k][b]
__device__ __align__(16) float g_hT[H * B];          // hidden transposed [k][b]
__device__ __align__(16) float g_yT[H2 * B];         // [h_new; ctx] transposed [k][b]
__device__ __align__(16) float g_logits[B * V];
__device__ __align__(16) float g_lpm[B * 512];
__device__ __align__(16) float g_lps[B * 512];
__device__ __align__(16) float g_lse[B];
__device__ int g_cnt0;
__device__ int g_cntA[B];
__device__ int g_cnt7;

__device__ __forceinline__ ull fma2(ull a, ull x, ull c) {
    asm("fma.rn.f32x2 %0, %1, %2, %3;" : "=l"(a) : "l"(x), "l"(c), "l"(a));
    return a;
}
__device__ __forceinline__ ull pack2(float w) {
    ull r;
    asm("mov.b64 %0, {%1, %1};" : "=l"(r) : "f"(w));
    return r;
}
__device__ __forceinline__ float lo32(ull a) { return __uint_as_float((unsigned)(a & 0xffffffffull)); }
__device__ __forceinline__ float hi32(ull a) { return __uint_as_float((unsigned)(a >> 32)); }

__device__ __forceinline__ void cpasync16(unsigned smem, const void* g) {
    asm volatile("cp.async.ca.shared.global [%0], [%1], 16;" :: "r"(smem), "l"(g));
}
#define CP_COMMIT() asm volatile("cp.async.commit_group;")
#define CP_WAIT0()  asm volatile("cp.async.wait_group 0;")

// ---------------- K0: w2 partials + bias + transposes + last-block combine --------
__global__ void k0_prep(const float* __restrict__ attn_W,
                        const float* __restrict__ attn_b,
                        const float* __restrict__ flatten,
                        const float* __restrict__ hidden,
                        const int*   __restrict__ input,
                        const float* __restrict__ emb_table)
{
    __shared__ float s_f[32];
    __shared__ float red[512];
    __shared__ float s_wh[H];
    __shared__ int s_last;
    int blk = blockIdx.x, tid = threadIdx.x;    // 512 threads, 9 blocks

    if (blk < 8) {
        if (tid < 32) s_f[tid] = flatten[blk * 32 + tid];
        __syncthreads();
        float acc = 0.f;
        #pragma unroll 8
        for (int i = 0; i < 32; i++)
            acc += attn_W[(size_t)(blk * 32 + i) * H2 + tid] * s_f[i];
        g_w2p[blk][tid] = acc;
    } else {
        red[tid] = (tid < H) ? flatten[tid] * attn_b[tid] : 0.f;
        __syncthreads();
        for (int s = 256; s > 0; s >>= 1) {
            if (tid < s) red[tid] += red[tid + s];
            __syncthreads();
        }
        if (tid == 0) g_bias = red[0];
        if (tid < 64) g_cntA[tid] = 0;
        if (tid == 64) g_cnt7 = 0;
        for (int idx = tid; idx < B * H; idx += 512) {
            int b = idx >> 8, j = idx & 255;
            g_xT[j * B + b] = emb_table[(size_t)input[b] * H + j];
            g_hT[j * B + b] = hidden[idx];
        }
    }

    // last-block combine: sum partials -> w2, compute e_h + bias
    __threadfence();
    __syncthreads();
    if (tid == 0) s_last = (atomicAdd(&g_cnt0, 1) == 8) ? 1 : 0;
    __syncthreads();
    if (!s_last) return;

    float w = 0.f;
    #pragma unroll
    for (int k = 0; k < 8; k++) w += g_w2p[k][tid];
    g_w2[tid] = w;
    if (tid < H) s_wh[tid] = w;
    __syncthreads();

    int wid = tid >> 5, lane = tid & 31;        // 16 warps x 4 b
    float bias = g_bias;
    #pragma unroll
    for (int i = 0; i < 4; i++) {
        int b = wid * 4 + i;
        float a = 0.f;
        #pragma unroll
        for (int c = 0; c < 8; c++) {
            int k = c * 32 + lane;
            a += hidden[b * H + k] * s_wh[k];
        }
        #pragma unroll
        for (int o = 16; o > 0; o >>= 1) a += __shfl_down_sync(0xffffffffu, a, o);
        if (lane == 0) g_ehb[b] = a + bias;
    }
    if (tid == 0) g_cnt0 = 0;                   // reset for graph replay
}

// ---------------- KA: fused energies + chunk softmax + partial ctx + combine ------
__global__ __launch_bounds__(256) void kA_attn(const float* __restrict__ enc,
                                               float* __restrict__ out_attn)
{
    extern __shared__ float sm[];
    float* tile = sm;                // 64*256
    float* s_w2 = sm + 64 * H;       // 256
    float* s_e  = s_w2 + H;          // 64
    float* s_w  = s_e + 64;          // 64
    float* s_m  = s_w + 64;          // 2
    int*   s_fl = (int*)(s_m + 2);

    int b = blockIdx.x >> 5;
    int c = blockIdx.x & 31;
    int tid = threadIdx.x;
    int l0 = c * 64;

    s_w2[tid] = g_w2[H + tid];

    const float4* src = (const float4*)(enc + ((size_t)l0 * B + b) * H);
    float4* t4 = (float4*)tile;
    #pragma unroll
    for (int i = 0; i < 16; i++) {
        int idx = tid + 256 * i;
        int row = idx >> 6, col = idx & 63;
        t4[row * 64 + col] = src[(size_t)row * 4096 + col];
    }
    __syncthreads();

    int wid = tid >> 5, lane = tid & 31;
    #pragma unroll
    for (int i = 0; i < 8; i++) {
        int l = wid * 8 + i;
        const float4* tr = (const float4*)(tile + l * H);
        const float4* w4 = (const float4*)s_w2;
        float4 t0 = tr[lane],      w0 = w4[lane];
        float4 t1 = tr[32 + lane], w1 = w4[32 + lane];
        float a = t0.x * w0.x + t0.y * w0.y + t0.z * w0.z + t0.w * w0.w
                + t1.x * w1.x + t1.y * w1.y + t1.z * w1.z + t1.w * w1.w;
        #pragma unroll
        for (int o = 16; o > 0; o >>= 1) a += __shfl_down_sync(0xffffffffu, a, o);
        if (lane == 0) {
            float e = a + g_ehb[b];
            s_e[l] = e;
            g_attn[b * L + l0 + l] = e;     // raw energy
        }
    }
    __syncthreads();

    if (wid == 0) {
        float m = fmaxf(s_e[lane], s_e[32 + lane]);
        #pragma unroll
        for (int o = 16; o > 0; o >>= 1) m = fmaxf(m, __shfl_xor_sync(0xffffffffu, m, o));
        if (lane == 0) s_m[0] = m;
    }
    __syncthreads();
    float m = s_m[0];
    if (tid < 64) s_w[tid] = __expf(s_e[tid] - m);
    __syncthreads();
    if (wid == 0) {
        float s = s_w[lane] + s_w[32 + lane];
        #pragma unroll
        for (int o = 16; o > 0; o >>= 1) s += __shfl_xor_sync(0xffffffffu, s, o);
        if (lane == 0) { g_pm[b * NCH + c] = m; g_ps[b * NCH + c] = s; }
    }
    __syncthreads();

    float a0 = 0.f, a1 = 0.f, a2 = 0.f, a3 = 0.f;
    #pragma unroll
    for (int l = 0; l < 64; l += 4) {
        a0 += s_w[l + 0] * tile[(l + 0) * H + tid];
        a1 += s_w[l + 1] * tile[(l + 1) * H + tid];
        a2 += s_w[l + 2] * tile[(l + 2) * H + tid];
        a3 += s_w[l + 3] * tile[(l + 3) * H + tid];
    }
    g_ctxp[(size_t)(b * NCH + c) * H + tid] = (a0 + a1) + (a2 + a3);

    __threadfence();
    __syncthreads();
    if (tid == 0) s_fl[0] = (atomicAdd(&g_cntA[b], 1) == NCH - 1) ? 1 : 0;
    __syncthreads();
    if (!s_fl[0]) return;

    float* s_scale = sm;            // 32 (tile no longer needed)
    float* s_mi    = sm + 32;       // 2
    if (tid < 32) {
        float mc = g_pm[b * NCH + tid];
        float sc = g_ps[b * NCH + tid];
        float mm = mc;
        #pragma unroll
        for (int o = 16; o > 0; o >>= 1) mm = fmaxf(mm, __shfl_xor_sync(0xffffffffu, mm, o));
        float sca = __expf(mc - mm);
        float ss = sc * sca;
        #pragma unroll
        for (int o = 16; o > 0; o >>= 1) ss += __shfl_xor_sync(0xffffffffu, ss, o);
        s_scale[tid] = sca;
        if (tid == 0) { s_mi[0] = mm; s_mi[1] = 1.f / ss; }
    }
    __syncthreads();
    float mg = s_mi[0], inv = s_mi[1];

    const float* cp = g_ctxp + (size_t)b * NCH * H + tid;
    float acc = 0.f;
    #pragma unroll 8
    for (int cc = 0; cc < NCH; cc++) acc += s_scale[cc] * cp[(size_t)cc * H];
    float ctxv = acc * inv;
    g_xT[(H + tid) * B + b] = ctxv;
    g_yT[(H + tid) * B + b] = ctxv;

    for (int l = tid; l < L; l += 256) {
        float w = __expf(g_attn[b * L + l] - mg) * inv;
        g_attn[b * L + l] = w;
        if (out_attn) out_attn[b * L + l] = w;
    }
}

// ---------------- K56: GRU, warp per j, lanes = b-pairs, no smem ------------------
__global__ __launch_bounds__(64) void k56_gru(const float* __restrict__ Wih,
                                              const float* __restrict__ Whh,
                                              const float* __restrict__ bih,
                                              const float* __restrict__ bhh,
                                              float* __restrict__ out_h)
{
    int j    = (blockIdx.x * 64 + threadIdx.x) >> 5;   // 0..255
    int lane = threadIdx.x & 31;

    const float* wr = Wih + (size_t)j * H2;
    const float* wz = Wih + (size_t)(j + H) * H2;
    const float* wn = Wih + (size_t)(j + 2 * H) * H2;

    ull ar = 0, az = 0, an = 0;
    #pragma unroll 8
    for (int k = 0; k < H2; k++) {
        ull x2 = *(const ull*)(g_xT + k * B + lane * 2);
        ar = fma2(ar, pack2(wr[k]), x2);
        az = fma2(az, pack2(wz[k]), x2);
        an = fma2(an, pack2(wn[k]), x2);
    }

    const float* hr = Whh + (size_t)j * H;
    const float* hz = Whh + (size_t)(j + H) * H;
    const float* hn = Whh + (size_t)(j + 2 * H) * H;

    ull br_ = 0, bz_ = 0, bn_ = 0;
    #pragma unroll 8
    for (int k = 0; k < H; k++) {
        ull h2 = *(const ull*)(g_hT + k * B + lane * 2);
        br_ = fma2(br_, pack2(hr[k]), h2);
        bz_ = fma2(bz_, pack2(hz[k]), h2);
        bn_ = fma2(bn_, pack2(hn[k]), h2);
    }

    float bir = bih[j], biz = bih[j + H], bin = bih[j + 2 * H];
    float bhr = bhh[j], bhz = bhh[j + H], bhn = bhh[j + 2 * H];
    float2 hp = *(const float2*)(g_hT + j * B + lane * 2);

    float hn_out[2];
    #pragma unroll
    for (int d = 0; d < 2; d++) {
        float gir = (d ? hi32(ar) : lo32(ar)) + bir;
        float giz = (d ? hi32(az) : lo32(az)) + biz;
        float gin = (d ? hi32(an) : lo32(an)) + bin;
        float ghr = (d ? hi32(br_) : lo32(br_)) + bhr;
        float ghz = (d ? hi32(bz_) : lo32(bz_)) + bhz;
        float ghn = (d ? hi32(bn_) : lo32(bn_)) + bhn;
        float r = 1.f / (1.f + __expf(-(gir + ghr)));
        float z = 1.f / (1.f + __expf(-(giz + ghz)));
        float n = tanhf(gin + r * ghn);
        float hprev = d ? hp.y : hp.x;
        hn_out[d] = (1.f - z) * n + z * hprev;
    }
    *(float2*)(g_yT + j * B + lane * 2) = make_float2(hn_out[0], hn_out[1]);
    if (out_h) {
        out_h[(lane * 2 + 0) * H + j] = hn_out[0];
        out_h[(lane * 2 + 1) * H + j] = hn_out[1];
    }
}

// ---------------- K7: logits GEMM, W pre-duplicated as f32x2 in smem --------------
// 500 blocks x (64v x 64b). y via cp.async double-buffer; W duplicated -> inner
// loop is LDS.64 + fma2 only (no pack2). 96KB smem -> 2 blocks/SM.
#define SOP 65
__global__ __launch_bounds__(256, 2) void k7_logits(const float* __restrict__ outW,
                                                    const float* __restrict__ outb)
{
    extern __shared__ float sm[];
    float* s_y = sm;                             // [2][64*64] floats, 32KB
    ull*   s_wd = (ull*)(sm + 2 * 4096);         // [2][64*64] ulls, 64KB
    int tid = threadIdx.x;
    int v0 = blockIdx.x * 64;
    int wid = tid >> 5, lane = tid & 31;

    const float4* W4 = (const float4*)outW;
    int r = tid >> 2;                            // v-local row for W staging
    int q = tid & 3;                             // base k-quad

    unsigned sy_base = (unsigned)__cvta_generic_to_shared(s_y);
    const float* ysrc = g_yT;

    // prologue: chunk 0
    #pragma unroll
    for (int i = 0; i < 4; i++)
        cpasync16(sy_base + (tid + 256 * i) * 16, ysrc + (tid + 256 * i) * 4);
    CP_COMMIT();
    {
        float4 rw[4];
        #pragma unroll
        for (int i = 0; i < 4; i++)
            rw[i] = W4[(size_t)(v0 + r) * 128 + q + 4 * i];
        #pragma unroll
        for (int i = 0; i < 4; i++) {
            ull* d = s_wd + r * 64 + (q + 4 * i) * 4;
            d[0] = pack2(rw[i].x); d[1] = pack2(rw[i].y);
            d[2] = pack2(rw[i].z); d[3] = pack2(rw[i].w);
        }
    }
    CP_WAIT0();
    __syncthreads();

    ull acc[8] = {0, 0, 0, 0, 0, 0, 0, 0};

    for (int c = 0; c < 8; c++) {
        float4 rw[4];
        int nb = (c + 1) & 1;
        if (c < 7) {
            // FIX (R6 bug): buffer offset is nb*16384 BYTES (4096 floats), not (nb*4096)*16
            #pragma unroll
            for (int i = 0; i < 4; i++)
                cpasync16(sy_base + nb * 16384 + (tid + 256 * i) * 16,
                          ysrc + ((c + 1) * 4096 + (tid + 256 * i) * 4));
            CP_COMMIT();
            #pragma unroll
            for (int i = 0; i < 4; i++)
                rw[i] = W4[(size_t)(v0 + r) * 128 + (c + 1) * 16 + q + 4 * i];
        }

        const float* yb = s_y + (c & 1) * 4096;
        const ull*   wb = s_wd + (c & 1) * 4096 + wid * 8 * 64;
        #pragma unroll 4
        for (int kk = 0; kk < 64; kk++) {
            ull y2 = *(const ull*)(yb + kk * 64 + lane * 2);
            #pragma unroll
            for (int j = 0; j < 8; j++)
                acc[j] = fma2(acc[j], wb[j * 64 + kk], y2);
        }

        if (c < 7) {
            #pragma unroll
            for (int i = 0; i < 4; i++) {
                ull* d = s_wd + nb * 4096 + r * 64 + (q + 4 * i) * 4;
                d[0] = pack2(rw[i].x); d[1] = pack2(rw[i].y);
                d[2] = pack2(rw[i].z); d[3] = pack2(rw[i].w);
            }
        }
        CP_WAIT0();
        __syncthreads();
    }

    // epilogue: stage 64b x 64v tile (pitch 65), add bias
    float* s_out = sm;
    #pragma unroll
    for (int j = 0; j < 8; j++) {
        int vl = wid * 8 + j;
        float bb = outb[v0 + vl];
        s_out[(lane * 2 + 0) * SOP + vl] = lo32(acc[j]) + bb;
        s_out[(lane * 2 + 1) * SOP + vl] = hi32(acc[j]) + bb;
    }
    __syncthreads();

    // coalesced float4 copy to g_logits
    #pragma unroll
    for (int it = 0; it < 4; it++) {
        int i = tid + 256 * it;
        int v4 = i & 15, b = i >> 4;
        const float* s = s_out + b * SOP + v4 * 4;
        *(float4*)(g_logits + (size_t)b * V + v0 + v4 * 4)
            = make_float4(s[0], s[1], s[2], s[3]);
    }

    // lse partials over this 64-v tile (4 threads per b)
    int bq = tid >> 2, i4 = tid & 3;
    {
        const float* rr = s_out + bq * SOP + i4 * 16;
        float m = -INFINITY;
        #pragma unroll
        for (int j = 0; j < 16; j++) m = fmaxf(m, rr[j]);
        m = fmaxf(m, __shfl_xor_sync(0xffffffffu, m, 1));
        m = fmaxf(m, __shfl_xor_sync(0xffffffffu, m, 2));
        float s = 0.f;
        #pragma unroll
        for (int j = 0; j < 16; j++) s += __expf(rr[j] - m);
        s += __shfl_xor_sync(0xffffffffu, s, 1);
        s += __shfl_xor_sync(0xffffffffu, s, 2);
        if (i4 == 0) {
            g_lpm[bq * 512 + blockIdx.x] = m;
            g_lps[bq * 512 + blockIdx.x] = s;
        }
    }

    // last block merges lse
    __shared__ int s_last;
    __threadfence();
    __syncthreads();
    if (tid == 0) s_last = (atomicAdd(&g_cnt7, 1) == NB7 - 1) ? 1 : 0;
    __syncthreads();
    if (!s_last) return;

    float m = -INFINITY;
    for (int i = i4; i < NB7; i += 4) m = fmaxf(m, g_lpm[bq * 512 + i]);
    m = fmaxf(m, __shfl_xor_sync(0xffffffffu, m, 1));
    m = fmaxf(m, __shfl_xor_sync(0xffffffffu, m, 2));
    float s = 0.f;
    for (int i = i4; i < NB7; i += 4)
        s += g_lps[bq * 512 + i] * __expf(g_lpm[bq * 512 + i] - m);
    s += __shfl_xor_sync(0xffffffffu, s, 1);
    s += __shfl_xor_sync(0xffffffffu, s, 2);
    if (i4 == 0) g_lse[bq] = m + logf(s);
}

// ---------------- K8w: out = logits - lse[b] ---------------------------------------
__global__ void k8w_write(float* __restrict__ out)
{
    int idx = blockIdx.x * 256 + threadIdx.x;   // float4 index
    int b = idx / (V / 4);
    float lse = g_lse[b];
    float4 v = ((const float4*)g_logits)[idx];
    v.x -= lse; v.y -= lse; v.z -= lse; v.w -= lse;
    ((float4*)out)[idx] = v;
}

// ---------------- host launch ------------------------------------------------------
extern "C" void kernel_launch(void* const* d_in, const int* in_sizes, int n_in,
                              void* d_out, int out_size)
{
    int s = (n_in >= 14 && in_sizes[3] == 1) ? 0 : -1;
    const int*   input    = (const int*)  d_in[0];
    const float* hidden   = (const float*)d_in[1];
    const float* enc      = (const float*)d_in[2];
    const float* emb      = (const float*)d_in[4 + s];
    const float* attn_W   = (const float*)d_in[5 + s];
    const float* attn_b   = (const float*)d_in[6 + s];
    const float* flatten  = (const float*)d_in[7 + s];
    const float* Wih      = (const float*)d_in[8 + s];
    const float* Whh      = (const float*)d_in[9 + s];
    const float* bih      = (const float*)d_in[10 + s];
    const float* bhh      = (const float*)d_in[11 + s];
    const float* outW     = (const float*)d_in[12 + s];
    const float* outb     = (const float*)d_in[13 + s];

    float* dout     = (float*)d_out;
    float* out_h    = (out_size >= B * V + B * H) ? dout + B * V : nullptr;
    float* out_attn = (out_size >= B * V + B * H + B * L) ? dout + B * V + B * H : nullptr;

    k0_prep<<<9, 512>>>(attn_W, attn_b, flatten, hidden, input, emb);

    int smem_kA = (64 * H + H + 64 + 64 + 2 + 2) * (int)sizeof(float);  // ~66.8KB
    cudaFuncSetAttribute(kA_attn, cudaFuncAttributeMaxDynamicSharedMemorySize, smem_kA);
    kA_attn<<<B * NCH, 256, smem_kA>>>(enc, out_attn);

    k56_gru<<<128, 64>>>(Wih, Whh, bih, bhh, out_h);

    int smem_k7 = (2 * 4096) * 4 + (2 * 4096) * 8;  // 32KB y + 64KB W = 98304 B
    cudaFuncSetAttribute(k7_logits, cudaFuncAttributeMaxDynamicSharedMemorySize, smem_k7);
    k7_logits<<<NB7, 256, smem_k7>>>(outW, outb);

    k8w_write<<<(B * V / 4) / 256, 256>>>(dout);
}

// round 9
// speedup vs baseline: 1.0675x; 1.0675x over previous
#include <cuda_runtime.h>
#include <math.h>

// Problem dims
#define H   256
#define H2  512
#define H3  768
#define B   64
#define L   2048
#define V   32000
#define CH  32              // kA: l-rows per block
#define NCHA 64             // kA: chunks per b
#define VT7 128             // k7: v per block
#define NB7 250             // k7 blocks (V/128)
#define KC  64              // k7 k-chunk

typedef unsigned long long ull;

// ---------------- scratch (device globals) ----------------------------------------
__device__ __align__(16) float g_w2p[8][H2];
__device__ __align__(16) float g_w2[H2];
__device__ float g_bias;
__device__ __align__(16) float g_ehb[B];
__device__ __align__(16) float g_attn[B * L];
__device__ __align__(16) float g_pm[B * NCHA];
__device__ __align__(16) float g_ps[B * NCHA];
__device__ __align__(16) float g_ctxp[B * NCHA * H];
__device__ __align__(16) float g_xT[H2 * B];         // [emb; ctx] transposed [k][b]
__device__ __align__(16) float g_hT[H * B];          // hidden transposed [k][b]
__device__ __align__(16) float g_yT[H2 * B];         // [h_new; ctx] transposed [k][b]
__device__ __align__(16) float g_logits[B * V];
__device__ __align__(16) float g_lpm[B * 256];
__device__ __align__(16) float g_lps[B * 256];
__device__ __align__(16) float g_lse[B];
__device__ int g_cnt0;
__device__ int g_cntA[B];
__device__ int g_cnt7;

__device__ __forceinline__ ull fma2(ull a, ull x, ull c) {
    asm("fma.rn.f32x2 %0, %1, %2, %3;" : "=l"(a) : "l"(x), "l"(c), "l"(a));
    return a;
}
__device__ __forceinline__ ull pack2(float w) {
    ull r;
    asm("mov.b64 %0, {%1, %1};" : "=l"(r) : "f"(w));
    return r;
}
__device__ __forceinline__ float lo32(ull a) { return __uint_as_float((unsigned)(a & 0xffffffffull)); }
__device__ __forceinline__ float hi32(ull a) { return __uint_as_float((unsigned)(a >> 32)); }
__device__ __forceinline__ float getc(float4 v, int c) {
    return c == 0 ? v.x : (c == 1 ? v.y : (c == 2 ? v.z : v.w));
}
__device__ __forceinline__ void cpasync16(unsigned smem, const void* g) {
    asm volatile("cp.async.ca.shared.global [%0], [%1], 16;" :: "r"(smem), "l"(g));
}
#define CP_COMMIT() asm volatile("cp.async.commit_group;")
#define CP_WAIT0()  asm volatile("cp.async.wait_group 0;")
#define CP_WAIT1()  asm volatile("cp.async.wait_group 1;")

// ---------------- K0: w2 partials + bias + transposes + last-block combine --------
__global__ void k0_prep(const float* __restrict__ attn_W,
                        const float* __restrict__ attn_b,
                        const float* __restrict__ flatten,
                        const float* __restrict__ hidden,
                        const int*   __restrict__ input,
                        const float* __restrict__ emb_table)
{
    __shared__ float s_f[32];
    __shared__ float red[512];
    __shared__ float s_wh[H];
    __shared__ int s_last;
    int blk = blockIdx.x, tid = threadIdx.x;    // 512 threads, 9 blocks

    if (blk < 8) {
        if (tid < 32) s_f[tid] = flatten[blk * 32 + tid];
        __syncthreads();
        float acc = 0.f;
        #pragma unroll 8
        for (int i = 0; i < 32; i++)
            acc += attn_W[(size_t)(blk * 32 + i) * H2 + tid] * s_f[i];
        g_w2p[blk][tid] = acc;
    } else {
        red[tid] = (tid < H) ? flatten[tid] * attn_b[tid] : 0.f;
        __syncthreads();
        for (int s = 256; s > 0; s >>= 1) {
            if (tid < s) red[tid] += red[tid + s];
            __syncthreads();
        }
        if (tid == 0) g_bias = red[0];
        if (tid < 64) g_cntA[tid] = 0;
        if (tid == 64) g_cnt7 = 0;
        for (int idx = tid; idx < B * H; idx += 512) {
            int b = idx >> 8, j = idx & 255;
            g_xT[j * B + b] = emb_table[(size_t)input[b] * H + j];
            g_hT[j * B + b] = hidden[idx];
        }
    }

    __threadfence();
    __syncthreads();
    if (tid == 0) s_last = (atomicAdd(&g_cnt0, 1) == 8) ? 1 : 0;
    __syncthreads();
    if (!s_last) return;

    float w = 0.f;
    #pragma unroll
    for (int k = 0; k < 8; k++) w += g_w2p[k][tid];
    g_w2[tid] = w;
    if (tid < H) s_wh[tid] = w;
    __syncthreads();

    int wid = tid >> 5, lane = tid & 31;        // 16 warps x 4 b
    float bias = g_bias;
    #pragma unroll
    for (int i = 0; i < 4; i++) {
        int b = wid * 4 + i;
        float a = 0.f;
        #pragma unroll
        for (int c = 0; c < 8; c++) {
            int k = c * 32 + lane;
            a += hidden[b * H + k] * s_wh[k];
        }
        #pragma unroll
        for (int o = 16; o > 0; o >>= 1) a += __shfl_down_sync(0xffffffffu, a, o);
        if (lane == 0) g_ehb[b] = a + bias;
    }
    if (tid == 0) g_cnt0 = 0;                   // reset for graph replay
}

// ---------------- KA: fused energies + chunk softmax + partial ctx + combine ------
// CH=32 rows, cp.async tile load, 4 blocks/SM.
__global__ __launch_bounds__(256) void kA_attn(const float* __restrict__ enc,
                                               float* __restrict__ out_attn)
{
    extern __shared__ float sm[];
    float* tile = sm;                // 32*256 = 8192 floats
    float* s_w2 = sm + CH * H;       // 256
    float* s_e  = s_w2 + H;          // 32
    float* s_w  = s_e + CH;          // 32
    float* s_m  = s_w + CH;          // 2
    float* s_sc = s_m + 2;           // 64 (combine scales)
    int*   s_fl = (int*)(s_sc + NCHA);

    int b = blockIdx.x >> 6;
    int c = blockIdx.x & 63;
    int tid = threadIdx.x;
    int l0 = c * CH;

    // async tile load: 2048 float4, 8 per thread
    unsigned tb_base = (unsigned)__cvta_generic_to_shared(tile);
    const float4* src = (const float4*)(enc + ((size_t)l0 * B + b) * H);
    #pragma unroll
    for (int i = 0; i < 8; i++) {
        int idx = tid + 256 * i;
        int row = idx >> 6, col = idx & 63;
        cpasync16(tb_base + (unsigned)idx * 16, src + (size_t)row * 4096 + col);
    }
    CP_COMMIT();
    s_w2[tid] = g_w2[H + tid];
    CP_WAIT0();
    __syncthreads();

    int wid = tid >> 5, lane = tid & 31;
    // energies: 8 warps x 4 l
    #pragma unroll
    for (int i = 0; i < 4; i++) {
        int l = wid * 4 + i;
        const float4* tr = (const float4*)(tile + l * H);
        const float4* w4 = (const float4*)s_w2;
        float4 t0 = tr[lane],      w0 = w4[lane];
        float4 t1 = tr[32 + lane], w1 = w4[32 + lane];
        float a = t0.x * w0.x + t0.y * w0.y + t0.z * w0.z + t0.w * w0.w
                + t1.x * w1.x + t1.y * w1.y + t1.z * w1.z + t1.w * w1.w;
        #pragma unroll
        for (int o = 16; o > 0; o >>= 1) a += __shfl_down_sync(0xffffffffu, a, o);
        if (lane == 0) {
            float e = a + g_ehb[b];
            s_e[l] = e;
            g_attn[b * L + l0 + l] = e;     // raw energy
        }
    }
    __syncthreads();

    if (wid == 0) {
        float m = s_e[lane];
        #pragma unroll
        for (int o = 16; o > 0; o >>= 1) m = fmaxf(m, __shfl_xor_sync(0xffffffffu, m, o));
        if (lane == 0) s_m[0] = m;
    }
    __syncthreads();
    float m = s_m[0];
    if (tid < CH) s_w[tid] = __expf(s_e[tid] - m);
    __syncthreads();
    if (wid == 0) {
        float s = s_w[lane];
        #pragma unroll
        for (int o = 16; o > 0; o >>= 1) s += __shfl_xor_sync(0xffffffffu, s, o);
        if (lane == 0) { g_pm[b * NCHA + c] = m; g_ps[b * NCHA + c] = s; }
    }
    __syncthreads();

    // partial context: thread = h
    float a0 = 0.f, a1 = 0.f, a2 = 0.f, a3 = 0.f;
    #pragma unroll
    for (int l = 0; l < CH; l += 4) {
        a0 += s_w[l + 0] * tile[(l + 0) * H + tid];
        a1 += s_w[l + 1] * tile[(l + 1) * H + tid];
        a2 += s_w[l + 2] * tile[(l + 2) * H + tid];
        a3 += s_w[l + 3] * tile[(l + 3) * H + tid];
    }
    g_ctxp[(size_t)(b * NCHA + c) * H + tid] = (a0 + a1) + (a2 + a3);

    __threadfence();
    __syncthreads();
    if (tid == 0) s_fl[0] = (atomicAdd(&g_cntA[b], 1) == NCHA - 1) ? 1 : 0;
    __syncthreads();
    if (!s_fl[0]) return;

    // combine: global max over 64 chunks
    if (wid == 0) {
        float m2 = fmaxf(g_pm[b * NCHA + lane], g_pm[b * NCHA + 32 + lane]);
        #pragma unroll
        for (int o = 16; o > 0; o >>= 1) m2 = fmaxf(m2, __shfl_xor_sync(0xffffffffu, m2, o));
        if (lane == 0) s_m[0] = m2;
    }
    __syncthreads();
    float mg = s_m[0];
    if (tid < NCHA) s_sc[tid] = __expf(g_pm[b * NCHA + tid] - mg);
    __syncthreads();
    if (wid == 0) {
        float ss = g_ps[b * NCHA + lane] * s_sc[lane]
                 + g_ps[b * NCHA + 32 + lane] * s_sc[32 + lane];
        #pragma unroll
        for (int o = 16; o > 0; o >>= 1) ss += __shfl_xor_sync(0xffffffffu, ss, o);
        if (lane == 0) s_m[1] = 1.f / ss;
    }
    __syncthreads();
    float inv = s_m[1];

    const float* cp = g_ctxp + (size_t)b * NCHA * H + tid;
    float acc = 0.f;
    #pragma unroll 8
    for (int cc = 0; cc < NCHA; cc++) acc += s_sc[cc] * cp[(size_t)cc * H];
    float ctxv = acc * inv;
    g_xT[(H + tid) * B + b] = ctxv;
    g_yT[(H + tid) * B + b] = ctxv;

    for (int l = tid; l < L; l += 256) {
        float w = __expf(g_attn[b * L + l] - mg) * inv;
        g_attn[b * L + l] = w;
        if (out_attn) out_attn[b * L + l] = w;
    }
}

// ---------------- K56: GRU, warp per j, lanes = b-pairs, no smem ------------------
__global__ __launch_bounds__(64) void k56_gru(const float* __restrict__ Wih,
                                              const float* __restrict__ Whh,
                                              const float* __restrict__ bih,
                                              const float* __restrict__ bhh,
                                              float* __restrict__ out_h)
{
    int j    = (blockIdx.x * 64 + threadIdx.x) >> 5;   // 0..255
    int lane = threadIdx.x & 31;

    const float* wr = Wih + (size_t)j * H2;
    const float* wz = Wih + (size_t)(j + H) * H2;
    const float* wn = Wih + (size_t)(j + 2 * H) * H2;

    ull ar = 0, az = 0, an = 0;
    #pragma unroll 8
    for (int k = 0; k < H2; k++) {
        ull x2 = *(const ull*)(g_xT + k * B + lane * 2);
        ar = fma2(ar, pack2(wr[k]), x2);
        az = fma2(az, pack2(wz[k]), x2);
        an = fma2(an, pack2(wn[k]), x2);
    }

    const float* hr = Whh + (size_t)j * H;
    const float* hz = Whh + (size_t)(j + H) * H;
    const float* hn = Whh + (size_t)(j + 2 * H) * H;

    ull br_ = 0, bz_ = 0, bn_ = 0;
    #pragma unroll 8
    for (int k = 0; k < H; k++) {
        ull h2 = *(const ull*)(g_hT + k * B + lane * 2);
        br_ = fma2(br_, pack2(hr[k]), h2);
        bz_ = fma2(bz_, pack2(hz[k]), h2);
        bn_ = fma2(bn_, pack2(hn[k]), h2);
    }

    float bir = bih[j], biz = bih[j + H], bin = bih[j + 2 * H];
    float bhr = bhh[j], bhz = bhh[j + H], bhn = bhh[j + 2 * H];
    float2 hp = *(const float2*)(g_hT + j * B + lane * 2);

    float hn_out[2];
    #pragma unroll
    for (int d = 0; d < 2; d++) {
        float gir = (d ? hi32(ar) : lo32(ar)) + bir;
        float giz = (d ? hi32(az) : lo32(az)) + biz;
        float gin = (d ? hi32(an) : lo32(an)) + bin;
        float ghr = (d ? hi32(br_) : lo32(br_)) + bhr;
        float ghz = (d ? hi32(bz_) : lo32(bz_)) + bhz;
        float ghn = (d ? hi32(bn_) : lo32(bn_)) + bhn;
        float r = 1.f / (1.f + __expf(-(gir + ghr)));
        float z = 1.f / (1.f + __expf(-(giz + ghz)));
        float n = tanhf(gin + r * ghn);
        float hprev = d ? hp.y : hp.x;
        hn_out[d] = (1.f - z) * n + z * hprev;
    }
    *(float2*)(g_yT + j * B + lane * 2) = make_float2(hn_out[0], hn_out[1]);
    if (out_h) {
        out_h[(lane * 2 + 0) * H + j] = hn_out[0];
        out_h[(lane * 2 + 1) * H + j] = hn_out[1];
    }
}

// ---------------- K7: register-blocked logits GEMM --------------------------------
// 250 blocks x (128v x 64b). Thread tile 4v x 8b. cp.async double-buffered chunks.
// W smem: pitch 76 + per-4-row swizzle -> conflict-free LDS.128 w-frags.
// FIX (R8 bug): pitch 68 overflowed (max in-row offset = 12 swizzle + 60 = 72 > 68),
// clobbering neighbor rows. Pitch 76 > 72; bank pattern unchanged ({0,20,8,28}).
#define WPITCH7 76
#define WBUF7   9744        // floats per W buffer (128*76 + pad)
#define SOP7    129
__global__ __launch_bounds__(256, 2) void k7_logits(const float* __restrict__ outW,
                                                    const float* __restrict__ outb)
{
    extern __shared__ float sm[];
    float* s_y = sm;                             // 2 x 4096 floats (32KB)
    float* s_w = sm + 8192;                      // 2 x 9744 floats (~76KB)
    int tid = threadIdx.x;
    int v0b = blockIdx.x * VT7;

    unsigned syb = (unsigned)__cvta_generic_to_shared(s_y);
    unsigned swb = (unsigned)__cvta_generic_to_shared(s_w);

    // ---- staging helper (chunk c into buffer buf) ----
    // y: 1024 float4 (4/thread); w: 2048 float4 (8/thread), swizzled rows
    #define K7_ISSUE(cc, buf) do {                                               \
        int _c = (cc), _bf = (buf);                                              \
        _Pragma("unroll")                                                        \
        for (int i = 0; i < 4; i++) {                                            \
            int idx = tid + 256 * i;                                             \
            cpasync16(syb + (unsigned)(_bf * 4096 + idx * 4) * 4,                \
                      g_yT + _c * 4096 + idx * 4);                               \
        }                                                                        \
        _Pragma("unroll")                                                        \
        for (int i = 0; i < 8; i++) {                                            \
            int idx = tid + 256 * i;                                             \
            int row = idx >> 4, q = idx & 15;                                    \
            int off = row * WPITCH7 + ((row >> 2) & 3) * 4 + q * 4;              \
            cpasync16(swb + (unsigned)(_bf * WBUF7 + off) * 4,                   \
                      outW + (size_t)(v0b + row) * H2 + _c * KC + q * 4);        \
        }                                                                        \
        CP_COMMIT();                                                             \
    } while (0)

    K7_ISSUE(0, 0);

    int bg = tid & 7;                            // 8 b-groups of 8
    int vgg = tid >> 3;                          // 32 v-groups of 4
    int v0 = vgg * 4;
    int wbase = v0 * WPITCH7 + (vgg & 3) * 4;

    ull acc[4][4];
    #pragma unroll
    for (int i = 0; i < 4; i++)
        #pragma unroll
        for (int p = 0; p < 4; p++) acc[i][p] = 0ull;

    for (int c = 0; c < 8; c++) {
        if (c < 7) { K7_ISSUE(c + 1, (c + 1) & 1); CP_WAIT1(); }
        else      { CP_WAIT0(); }
        __syncthreads();

        const float* yb = s_y + (c & 1) * 4096;
        const float* wb = s_w + (c & 1) * WBUF7;

        #pragma unroll 2
        for (int kq = 0; kq < 16; kq++) {
            float4 w4[4];
            #pragma unroll
            for (int i = 0; i < 4; i++)
                w4[i] = *(const float4*)(wb + wbase + i * WPITCH7 + kq * 4);
            #pragma unroll
            for (int kk = 0; kk < 4; kk++) {
                int k = kq * 4 + kk;
                ulonglong2 ya = *(const ulonglong2*)(yb + k * 64 + bg * 8);
                ulonglong2 yc = *(const ulonglong2*)(yb + k * 64 + bg * 8 + 4);
                #pragma unroll
                for (int i = 0; i < 4; i++) {
                    ull w2 = pack2(getc(w4[i], kk));
                    acc[i][0] = fma2(acc[i][0], w2, ya.x);
                    acc[i][1] = fma2(acc[i][1], w2, ya.y);
                    acc[i][2] = fma2(acc[i][2], w2, yc.x);
                    acc[i][3] = fma2(acc[i][3], w2, yc.y);
                }
            }
        }
        __syncthreads();
    }

    // epilogue: stage 64b x 128v tile (pitch 129), add bias
    float* s_out = sm;                           // reuse (64*129*4 = 33KB)
    #pragma unroll
    for (int i = 0; i < 4; i++) {
        float bb = outb[v0b + v0 + i];
        #pragma unroll
        for (int p = 0; p < 4; p++) {
            s_out[(bg * 8 + 2 * p + 0) * SOP7 + v0 + i] = lo32(acc[i][p]) + bb;
            s_out[(bg * 8 + 2 * p + 1) * SOP7 + v0 + i] = hi32(acc[i][p]) + bb;
        }
    }
    __syncthreads();

    // coalesced float4 copy to g_logits: 2048 float4
    #pragma unroll
    for (int it = 0; it < 8; it++) {
        int i = tid + 256 * it;
        int v4 = i & 31, b = i >> 5;
        const float* s = s_out + b * SOP7 + v4 * 4;
        *(float4*)(g_logits + (size_t)b * V + v0b + v4 * 4)
            = make_float4(s[0], s[1], s[2], s[3]);
    }

    // lse partials over this 128-v tile (4 threads per b, 32 v each)
    int bq = tid >> 2, i4 = tid & 3;
    {
        const float* rr = s_out + bq * SOP7 + i4 * 32;
        float m = -INFINITY;
        #pragma unroll
        for (int j = 0; j < 32; j++) m = fmaxf(m, rr[j]);
        m = fmaxf(m, __shfl_xor_sync(0xffffffffu, m, 1));
        m = fmaxf(m, __shfl_xor_sync(0xffffffffu, m, 2));
        float s = 0.f;
        #pragma unroll
        for (int j = 0; j < 32; j++) s += __expf(rr[j] - m);
        s += __shfl_xor_sync(0xffffffffu, s, 1);
        s += __shfl_xor_sync(0xffffffffu, s, 2);
        if (i4 == 0) {
            g_lpm[bq * 256 + blockIdx.x] = m;
            g_lps[bq * 256 + blockIdx.x] = s;
        }
    }

    // last block merges lse
    __shared__ int s_last;
    __threadfence();
    __syncthreads();
    if (tid == 0) s_last = (atomicAdd(&g_cnt7, 1) == NB7 - 1) ? 1 : 0;
    __syncthreads();
    if (!s_last) return;

    float m = -INFINITY;
    for (int i = i4; i < NB7; i += 4) m = fmaxf(m, g_lpm[bq * 256 + i]);
    m = fmaxf(m, __shfl_xor_sync(0xffffffffu, m, 1));
    m = fmaxf(m, __shfl_xor_sync(0xffffffffu, m, 2));
    float s = 0.f;
    for (int i = i4; i < NB7; i += 4)
        s += g_lps[bq * 256 + i] * __expf(g_lpm[bq * 256 + i] - m);
    s += __shfl_xor_sync(0xffffffffu, s, 1);
    s += __shfl_xor_sync(0xffffffffu, s, 2);
    if (i4 == 0) g_lse[bq] = m + logf(s);
}

// ---------------- K8w: out = logits - lse[b] ---------------------------------------
__global__ void k8w_write(float* __restrict__ out)
{
    int idx = blockIdx.x * 256 + threadIdx.x;   // float4 index
    int b = idx / (V / 4);
    float lse = g_lse[b];
    float4 v = ((const float4*)g_logits)[idx];
    v.x -= lse; v.y -= lse; v.z -= lse; v.w -= lse;
    ((float4*)out)[idx] = v;
}

// ---------------- host launch ------------------------------------------------------
extern "C" void kernel_launch(void* const* d_in, const int* in_sizes, int n_in,
                              void* d_out, int out_size)
{
    int s = (n_in >= 14 && in_sizes[3] == 1) ? 0 : -1;
    const int*   input    = (const int*)  d_in[0];
    const float* hidden   = (const float*)d_in[1];
    const float* enc      = (const float*)d_in[2];
    const float* emb      = (const float*)d_in[4 + s];
    const float* attn_W   = (const float*)d_in[5 + s];
    const float* attn_b   = (const float*)d_in[6 + s];
    const float* flatten  = (const float*)d_in[7 + s];
    const float* Wih      = (const float*)d_in[8 + s];
    const float* Whh      = (const float*)d_in[9 + s];
    const float* bih      = (const float*)d_in[10 + s];
    const float* bhh      = (const float*)d_in[11 + s];
    const float* outW     = (const float*)d_in[12 + s];
    const float* outb     = (const float*)d_in[13 + s];

    float* dout     = (float*)d_out;
    float* out_h    = (out_size >= B * V + B * H) ? dout + B * V : nullptr;
    float* out_attn = (out_size >= B * V + B * H + B * L) ? dout + B * V + B * H : nullptr;

    k0_prep<<<9, 512>>>(attn_W, attn_b, flatten, hidden, input, emb);

    int smem_kA = (CH * H + H + CH + CH + 2 + NCHA + 4) * (int)sizeof(float);  // ~33.6KB
    cudaFuncSetAttribute(kA_attn, cudaFuncAttributeMaxDynamicSharedMemorySize, smem_kA);
    kA_attn<<<B * NCHA, 256, smem_kA>>>(enc, out_attn);

    k56_gru<<<128, 64>>>(Wih, Whh, bih, bhh, out_h);

    int smem_k7 = (2 * 4096 + 2 * WBUF7) * (int)sizeof(float);  // 110720 B
    cudaFuncSetAttribute(k7_logits, cudaFuncAttributeMaxDynamicSharedMemorySize, smem_k7);
    k7_logits<<<NB7, 256, smem_k7>>>(outW, outb);

    k8w_write<<<(B * V / 4) / 256, 256>>>(dout);
}

// round 11
// speedup vs baseline: 1.0903x; 1.0214x over previous
#include <cuda_runtime.h>
#include <math.h>

// Problem dims
#define H   256
#define H2  512
#define B   64
#define L   2048
#define V   32000
#define NG  4               // kA: groups per b
#define NCHG 16             // kA: chunks per group (32 l each)
#define NB7 125             // k7 blocks (V/256)
#define VT7 256
#define WP7 33
#define WBUF7 8448          // 256*33

typedef unsigned long long ull;

// ---------------- scratch (device globals) ----------------------------------------
__device__ __align__(16) float g_w2p[8][H2];
__device__ __align__(16) float g_w2[H2];
__device__ float g_bias;
__device__ __align__(16) float g_ehb[B];
__device__ __align__(16) float g_attn[B * L];        // raw energies
__device__ __align__(16) float g_pm[B * NG];
__device__ __align__(16) float g_ps[B * NG];
__device__ __align__(16) float g_ctxp[B * NG * H];
__device__ __align__(16) float g_xT[H2 * B];         // [emb; ctx] transposed [k][b]
__device__ __align__(16) float g_hT[H * B];          // hidden transposed [k][b]
__device__ __align__(16) float g_yT[H2 * B];         // [h_new; ctx] transposed [k][b]
__device__ __align__(16) float g_logits[B * V];
__device__ __align__(16) float g_lpm[B * 128];
__device__ __align__(16) float g_lps[B * 128];
__device__ __align__(16) float g_lse[B];
__device__ int g_cnt0;
__device__ int g_cnt7;

__device__ __forceinline__ ull fma2(ull a, ull x, ull c) {
    asm("fma.rn.f32x2 %0, %1, %2, %3;" : "=l"(a) : "l"(x), "l"(c), "l"(a));
    return a;
}
__device__ __forceinline__ ull pack2(float w) {
    ull r;
    asm("mov.b64 %0, {%1, %1};" : "=l"(r) : "f"(w));
    return r;
}
__device__ __forceinline__ float lo32(ull a) { return __uint_as_float((unsigned)(a & 0xffffffffull)); }
__device__ __forceinline__ float hi32(ull a) { return __uint_as_float((unsigned)(a >> 32)); }
__device__ __forceinline__ void cpasync16(unsigned smem, const void* g) {
    asm volatile("cp.async.ca.shared.global [%0], [%1], 16;" :: "r"(smem), "l"(g));
}
__device__ __forceinline__ void cpasync4(unsigned smem, const void* g) {
    asm volatile("cp.async.ca.shared.global [%0], [%1], 4;" :: "r"(smem), "l"(g));
}
#define CP_COMMIT() asm volatile("cp.async.commit_group;")
#define CP_WAIT0()  asm volatile("cp.async.wait_group 0;")
#define CP_WAIT1()  asm volatile("cp.async.wait_group 1;")

// ---------------- K0: w2 partials + bias + transposes + last-block combine --------
__global__ void k0_prep(const float* __restrict__ attn_W,
                        const float* __restrict__ attn_b,
                        const float* __restrict__ flatten,
                        const float* __restrict__ hidden,
                        const int*   __restrict__ input,
                        const float* __restrict__ emb_table)
{
    __shared__ float s_f[32];
    __shared__ float red[512];
    __shared__ float s_wh[H];
    __shared__ int s_last;
    int blk = blockIdx.x, tid = threadIdx.x;    // 512 threads, 9 blocks

    if (blk < 8) {
        if (tid < 32) s_f[tid] = flatten[blk * 32 + tid];
        __syncthreads();
        float acc = 0.f;
        #pragma unroll 8
        for (int i = 0; i < 32; i++)
            acc += attn_W[(size_t)(blk * 32 + i) * H2 + tid] * s_f[i];
        g_w2p[blk][tid] = acc;
    } else {
        red[tid] = (tid < H) ? flatten[tid] * attn_b[tid] : 0.f;
        __syncthreads();
        for (int s = 256; s > 0; s >>= 1) {
            if (tid < s) red[tid] += red[tid + s];
            __syncthreads();
        }
        if (tid == 0) g_bias = red[0];
        if (tid == 1) g_cnt7 = 0;
        for (int idx = tid; idx < B * H; idx += 512) {
            int b = idx >> 8, j = idx & 255;
            g_xT[j * B + b] = emb_table[(size_t)input[b] * H + j];
            g_hT[j * B + b] = hidden[idx];
        }
    }

    __threadfence();
    __syncthreads();
    if (tid == 0) s_last = (atomicAdd(&g_cnt0, 1) == 8) ? 1 : 0;
    __syncthreads();
    if (!s_last) return;

    float w = 0.f;
    #pragma unroll
    for (int k = 0; k < 8; k++) w += g_w2p[k][tid];
    g_w2[tid] = w;
    if (tid < H) s_wh[tid] = w;
    __syncthreads();

    int wid = tid >> 5, lane = tid & 31;        // 16 warps x 4 b
    float bias = g_bias;
    #pragma unroll
    for (int i = 0; i < 4; i++) {
        int b = wid * 4 + i;
        float a = 0.f;
        #pragma unroll
        for (int c = 0; c < 8; c++) {
            int k = c * 32 + lane;
            a += hidden[b * H + k] * s_wh[k];
        }
        #pragma unroll
        for (int o = 16; o > 0; o >>= 1) a += __shfl_down_sync(0xffffffffu, a, o);
        if (lane == 0) g_ehb[b] = a + bias;
    }
    if (tid == 0) g_cnt0 = 0;                   // reset for graph replay
}

// ---------------- KA-v2: pipelined energies + online-softmax context --------------
// 256 blocks (b x 4 groups), 16 chunks of 32 l each, double-buffered cp.async.
__global__ __launch_bounds__(256) void kA_attn(const float* __restrict__ enc)
{
    extern __shared__ float sm[];
    // [0:16384)   two 32x256 tiles
    float* s_w2 = sm + 16384;        // 256
    float* s_e  = s_w2 + H;          // 32
    float* s_w  = s_e + 32;          // 32
    float* s_st = s_w + 32;          // [0]=m_run [1]=s_run [2]=m_new [3]=scale_old

    int b = blockIdx.x >> 2;
    int g = blockIdx.x & 3;
    int tid = threadIdx.x;
    int wid = tid >> 5, lane = tid & 31;

    unsigned tb = (unsigned)__cvta_generic_to_shared(sm);
    const float4* src0 = (const float4*)(enc + (size_t)b * H);   // + l*B*H

    // prologue: chunk 0 into buf 0
    {
        int l0 = (g * NCHG) * 32;
        #pragma unroll
        for (int i = 0; i < 8; i++) {
            int idx = tid + 256 * i;
            int row = idx >> 6, col = idx & 63;
            cpasync16(tb + (unsigned)idx * 16, src0 + (size_t)(l0 + row) * 4096 + col);
        }
        CP_COMMIT();
    }
    s_w2[tid] = g_w2[H + tid];
    if (tid == 0) { s_st[0] = -INFINITY; s_st[1] = 0.f; }
    float ehb = g_ehb[b];
    float ctx_acc = 0.f;

    for (int i = 0; i < NCHG; i++) {
        if (i < NCHG - 1) {
            int l0 = (g * NCHG + i + 1) * 32;
            unsigned dst = tb + (unsigned)(((i + 1) & 1) * 8192) * 4;
            #pragma unroll
            for (int t = 0; t < 8; t++) {
                int idx = tid + 256 * t;
                int row = idx >> 6, col = idx & 63;
                cpasync16(dst + (unsigned)idx * 16, src0 + (size_t)(l0 + row) * 4096 + col);
            }
            CP_COMMIT();
            CP_WAIT1();
        } else {
            CP_WAIT0();
        }
        __syncthreads();

        float* tile = sm + (i & 1) * 8192;
        int l0 = (g * NCHG + i) * 32;

        // energies: 8 warps x 4 l
        #pragma unroll
        for (int r = 0; r < 4; r++) {
            int l = wid * 4 + r;
            const float4* tr = (const float4*)(tile + l * H);
            const float4* w4 = (const float4*)s_w2;
            float4 t0 = tr[lane],      w0 = w4[lane];
            float4 t1 = tr[32 + lane], w1 = w4[32 + lane];
            float a = t0.x * w0.x + t0.y * w0.y + t0.z * w0.z + t0.w * w0.w
                    + t1.x * w1.x + t1.y * w1.y + t1.z * w1.z + t1.w * w1.w;
            #pragma unroll
            for (int o = 16; o > 0; o >>= 1) a += __shfl_down_sync(0xffffffffu, a, o);
            if (lane == 0) {
                float e = a + ehb;
                s_e[l] = e;
                g_attn[b * L + l0 + l] = e;     // raw energy
            }
        }
        __syncthreads();

        // online max update
        if (wid == 0) {
            float m = s_e[lane];
            #pragma unroll
            for (int o = 16; o > 0; o >>= 1) m = fmaxf(m, __shfl_xor_sync(0xffffffffu, m, o));
            if (lane == 0) {
                float m_new = fmaxf(s_st[0], m);
                s_st[2] = m_new;
                s_st[3] = __expf(s_st[0] - m_new);
                s_st[0] = m_new;
            }
        }
        __syncthreads();
        float m_new = s_st[2], sc_old = s_st[3];
        if (tid < 32) s_w[tid] = __expf(s_e[tid] - m_new);
        __syncthreads();
        if (wid == 0) {
            float s = s_w[lane];
            #pragma unroll
            for (int o = 16; o > 0; o >>= 1) s += __shfl_xor_sync(0xffffffffu, s, o);
            if (lane == 0) s_st[1] = s_st[1] * sc_old + s;
        }

        // running context (thread = h)
        float a0 = 0.f, a1 = 0.f, a2 = 0.f, a3 = 0.f;
        #pragma unroll
        for (int l = 0; l < 32; l += 4) {
            a0 += s_w[l + 0] * tile[(l + 0) * H + tid];
            a1 += s_w[l + 1] * tile[(l + 1) * H + tid];
            a2 += s_w[l + 2] * tile[(l + 2) * H + tid];
            a3 += s_w[l + 3] * tile[(l + 3) * H + tid];
        }
        ctx_acc = ctx_acc * sc_old + ((a0 + a1) + (a2 + a3));
        // no trailing sync: next iter's top sync protects all shared state
    }

    g_ctxp[(size_t)(b * NG + g) * H + tid] = ctx_acc;
    if (tid == 0) { g_pm[b * NG + g] = s_st[0]; g_ps[b * NG + g] = s_st[1]; }
}

// ---------------- KB: combine 4 group partials -> ctx, attn weights ---------------
__global__ void kB_combine(float* __restrict__ out_attn)
{
    __shared__ float s_sc[NG];
    __shared__ float s_mi[2];
    int b = blockIdx.x, tid = threadIdx.x;      // 256 threads

    if (tid < 32) {
        float mc = (tid < NG) ? g_pm[b * NG + tid] : -INFINITY;
        float sc = (tid < NG) ? g_ps[b * NG + tid] : 0.f;
        float m = mc;
        #pragma unroll
        for (int o = 2; o > 0; o >>= 1) m = fmaxf(m, __shfl_xor_sync(0xffffffffu, m, o));
        m = __shfl_sync(0xffffffffu, m, 0, 4);
        float sca = __expf(mc - m);
        float s = sc * sca;
        #pragma unroll
        for (int o = 2; o > 0; o >>= 1) s += __shfl_xor_sync(0xffffffffu, s, o);
        if (tid < NG) s_sc[tid] = sca;
        if (tid == 0) { s_mi[0] = m; s_mi[1] = 1.f / s; }
    }
    __syncthreads();
    float mg = s_mi[0], inv = s_mi[1];

    float acc = 0.f;
    #pragma unroll
    for (int g = 0; g < NG; g++)
        acc += s_sc[g] * g_ctxp[(size_t)(b * NG + g) * H + tid];
    float ctxv = acc * inv;
    g_xT[(H + tid) * B + b] = ctxv;
    g_yT[(H + tid) * B + b] = ctxv;

    if (out_attn)
        for (int l = tid; l < L; l += 256)
            out_attn[b * L + l] = __expf(g_attn[b * L + l] - mg) * inv;
}

// ---------------- K56: GRU, warp per j, lanes = b-pairs ---------------------------
__global__ __launch_bounds__(64) void k56_gru(const float* __restrict__ Wih,
                                              const float* __restrict__ Whh,
                                              const float* __restrict__ bih,
                                              const float* __restrict__ bhh,
                                              float* __restrict__ out_h)
{
    int j    = (blockIdx.x * 64 + threadIdx.x) >> 5;   // 0..255
    int lane = threadIdx.x & 31;

    const float* wr = Wih + (size_t)j * H2;
    const float* wz = Wih + (size_t)(j + H) * H2;
    const float* wn = Wih + (size_t)(j + 2 * H) * H2;

    ull ar = 0, az = 0, an = 0;
    #pragma unroll 8
    for (int k = 0; k < H2; k++) {
        ull x2 = *(const ull*)(g_xT + k * B + lane * 2);
        ar = fma2(ar, pack2(wr[k]), x2);
        az = fma2(az, pack2(wz[k]), x2);
        an = fma2(an, pack2(wn[k]), x2);
    }

    const float* hr = Whh + (size_t)j * H;
    const float* hz = Whh + (size_t)(j + H) * H;
    const float* hn = Whh + (size_t)(j + 2 * H) * H;

    ull br_ = 0, bz_ = 0, bn_ = 0;
    #pragma unroll 8
    for (int k = 0; k < H; k++) {
        ull h2 = *(const ull*)(g_hT + k * B + lane * 2);
        br_ = fma2(br_, pack2(hr[k]), h2);
        bz_ = fma2(bz_, pack2(hz[k]), h2);
        bn_ = fma2(bn_, pack2(hn[k]), h2);
    }

    float bir = bih[j], biz = bih[j + H], bin = bih[j + 2 * H];
    float bhr = bhh[j], bhz = bhh[j + H], bhn = bhh[j + 2 * H];
    float2 hp = *(const float2*)(g_hT + j * B + lane * 2);

    float hn_out[2];
    #pragma unroll
    for (int d = 0; d < 2; d++) {
        float gir = (d ? hi32(ar) : lo32(ar)) + bir;
        float giz = (d ? hi32(az) : lo32(az)) + biz;
        float gin = (d ? hi32(an) : lo32(an)) + bin;
        float ghr = (d ? hi32(br_) : lo32(br_)) + bhr;
        float ghz = (d ? hi32(bz_) : lo32(bz_)) + bhz;
        float ghn = (d ? hi32(bn_) : lo32(bn_)) + bhn;
        float r = 1.f / (1.f + __expf(-(gir + ghr)));
        float z = 1.f / (1.f + __expf(-(giz + ghz)));
        float n = tanhf(gin + r * ghn);
        float hprev = d ? hp.y : hp.x;
        hn_out[d] = (1.f - z) * n + z * hprev;
    }
    *(float2*)(g_yT + j * B + lane * 2) = make_float2(hn_out[0], hn_out[1]);
    if (out_h) {
        out_h[(lane * 2 + 0) * H + j] = hn_out[0];
        out_h[(lane * 2 + 1) * H + j] = hn_out[1];
    }
}

// ---------------- K7: logits GEMM, y resident in smem, 512 threads ---------------
// 125 blocks x (256v x 64b), 16 warps/SM, thread tile 4v x 8b.
// W double-buffered (pitch 33, scalar broadcast reads -> conflict-free banks
// {b,b+4,b+8,b+12}), y loaded once (128KB).
// FIX (R10 bug): W staging used 16B cp.async to row*33*4-byte offsets, which are
// only 4B-aligned for odd rows -> misaligned address. Stage W with 4-byte
// cp.async instead (alignment requirement = copy size); source stays coalesced.
#define SOP7 257
__global__ __launch_bounds__(512) void k7_logits(const float* __restrict__ outW,
                                                 const float* __restrict__ outb)
{
    extern __shared__ float sm[];
    float* s_y = sm;                             // 32768 floats (128KB)
    float* s_w = sm + 32768;                     // 2 x 8448 floats (~67.6KB)
    int tid = threadIdx.x;
    int v0b = blockIdx.x * VT7;

    unsigned syb = (unsigned)__cvta_generic_to_shared(s_y);
    unsigned swb = (unsigned)__cvta_generic_to_shared(s_w);

    // W chunk staging: 8192 scalars, 16/thread, 4-byte cp.async (any alignment ok)
    #define K7_ISSUE_W(cc, buf) do {                                             \
        int _c = (cc), _bf = (buf);                                              \
        _Pragma("unroll")                                                        \
        for (int t = 0; t < 16; t++) {                                           \
            int idx = tid + 512 * t;                                             \
            int row = idx >> 5, k = idx & 31;                                    \
            cpasync4(swb + (unsigned)(_bf * WBUF7 + row * WP7 + k) * 4,          \
                     outW + (size_t)(v0b + row) * H2 + _c * 32 + k);             \
        }                                                                        \
    } while (0)

    // prologue: full y (8192 f4, 16/thread) + W chunk 0, one group
    #pragma unroll
    for (int t = 0; t < 16; t++) {
        int idx = tid + 512 * t;
        cpasync16(syb + (unsigned)idx * 16, g_yT + idx * 4);
    }
    K7_ISSUE_W(0, 0);
    CP_COMMIT();

    int bg = tid & 7;                            // 8 b-groups of 8
    int tv = tid >> 3;                           // 64 v-groups of 4
    int vl = tv * 4;
    int b0 = bg * 8;

    ull acc[4][4];
    #pragma unroll
    for (int i = 0; i < 4; i++)
        #pragma unroll
        for (int p = 0; p < 4; p++) acc[i][p] = 0ull;

    for (int c = 0; c < 16; c++) {
        if (c < 15) { K7_ISSUE_W(c + 1, (c + 1) & 1); CP_COMMIT(); CP_WAIT1(); }
        else        { CP_WAIT0(); }
        __syncthreads();

        const float* wb = s_w + (c & 1) * WBUF7;
        #pragma unroll 4
        for (int kk = 0; kk < 32; kk++) {
            int k = c * 32 + kk;
            ulonglong2 ya = *(const ulonglong2*)(s_y + k * 64 + b0);
            ulonglong2 yc = *(const ulonglong2*)(s_y + k * 64 + b0 + 4);
            #pragma unroll
            for (int i = 0; i < 4; i++) {
                ull w2 = pack2(wb[(vl + i) * WP7 + kk]);
                acc[i][0] = fma2(acc[i][0], w2, ya.x);
                acc[i][1] = fma2(acc[i][1], w2, ya.y);
                acc[i][2] = fma2(acc[i][2], w2, yc.x);
                acc[i][3] = fma2(acc[i][3], w2, yc.y);
            }
        }
    }
    __syncthreads();                             // all reads of s_y done

    // epilogue: stage 64b x 256v tile (pitch 257) in s_y region, add bias
    float* s_out = sm;
    #pragma unroll
    for (int i = 0; i < 4; i++) {
        float bb = outb[v0b + vl + i];
        #pragma unroll
        for (int p = 0; p < 4; p++) {
            s_out[(b0 + 2 * p + 0) * SOP7 + vl + i] = lo32(acc[i][p]) + bb;
            s_out[(b0 + 2 * p + 1) * SOP7 + vl + i] = hi32(acc[i][p]) + bb;
        }
    }
    __syncthreads();

    // coalesced float4 copy: 4096 f4, 8/thread
    #pragma unroll
    for (int t = 0; t < 8; t++) {
        int i = tid + 512 * t;
        int v4 = i & 63, b = i >> 6;
        const float* s = s_out + b * SOP7 + v4 * 4;
        *(float4*)(g_logits + (size_t)b * V + v0b + v4 * 4)
            = make_float4(s[0], s[1], s[2], s[3]);
    }

    // lse partials: 8 threads per b, 32 v each
    int bq = tid >> 3, i8 = tid & 7;
    {
        const float* rr = s_out + bq * SOP7 + i8 * 32;
        float m = -INFINITY;
        #pragma unroll
        for (int j = 0; j < 32; j++) m = fmaxf(m, rr[j]);
        #pragma unroll
        for (int o = 4; o > 0; o >>= 1) m = fmaxf(m, __shfl_xor_sync(0xffffffffu, m, o));
        float s = 0.f;
        #pragma unroll
        for (int j = 0; j < 32; j++) s += __expf(rr[j] - m);
        #pragma unroll
        for (int o = 4; o > 0; o >>= 1) s += __shfl_xor_sync(0xffffffffu, s, o);
        if (i8 == 0) {
            g_lpm[bq * 128 + blockIdx.x] = m;
            g_lps[bq * 128 + blockIdx.x] = s;
        }
    }

    // last block merges lse
    __shared__ int s_last;
    __threadfence();
    __syncthreads();
    if (tid == 0) s_last = (atomicAdd(&g_cnt7, 1) == NB7 - 1) ? 1 : 0;
    __syncthreads();
    if (!s_last) return;

    float m = -INFINITY;
    for (int i = i8; i < NB7; i += 8) m = fmaxf(m, g_lpm[bq * 128 + i]);
    #pragma unroll
    for (int o = 4; o > 0; o >>= 1) m = fmaxf(m, __shfl_xor_sync(0xffffffffu, m, o));
    float s = 0.f;
    for (int i = i8; i < NB7; i += 8)
        s += g_lps[bq * 128 + i] * __expf(g_lpm[bq * 128 + i] - m);
    #pragma unroll
    for (int o = 4; o > 0; o >>= 1) s += __shfl_xor_sync(0xffffffffu, s, o);
    if (i8 == 0) g_lse[bq] = m + logf(s);
}

// ---------------- K8w: out = logits - lse[b] ---------------------------------------
__global__ void k8w_write(float* __restrict__ out)
{
    int idx = blockIdx.x * 256 + threadIdx.x;   // float4 index
    int b = idx / (V / 4);
    float lse = g_lse[b];
    float4 v = ((const float4*)g_logits)[idx];
    v.x -= lse; v.y -= lse; v.z -= lse; v.w -= lse;
    ((float4*)out)[idx] = v;
}

// ---------------- host launch ------------------------------------------------------
extern "C" void kernel_launch(void* const* d_in, const int* in_sizes, int n_in,
                              void* d_out, int out_size)
{
    int s = (n_in >= 14 && in_sizes[3] == 1) ? 0 : -1;
    const int*   input    = (const int*)  d_in[0];
    const float* hidden   = (const float*)d_in[1];
    const float* enc      = (const float*)d_in[2];
    const float* emb      = (const float*)d_in[4 + s];
    const float* attn_W   = (const float*)d_in[5 + s];
    const float* attn_b   = (const float*)d_in[6 + s];
    const float* flatten  = (const float*)d_in[7 + s];
    const float* Wih      = (const float*)d_in[8 + s];
    const float* Whh      = (const float*)d_in[9 + s];
    const float* bih      = (const float*)d_in[10 + s];
    const float* bhh      = (const float*)d_in[11 + s];
    const float* outW     = (const float*)d_in[12 + s];
    const float* outb     = (const float*)d_in[13 + s];

    float* dout     = (float*)d_out;
    float* out_h    = (out_size >= B * V + B * H) ? dout + B * V : nullptr;
    float* out_attn = (out_size >= B * V + B * H + B * L) ? dout + B * V + B * H : nullptr;

    k0_prep<<<9, 512>>>(attn_W, attn_b, flatten, hidden, input, emb);

    int smem_kA = (16384 + 256 + 32 + 32 + 8) * (int)sizeof(float);  // ~66.8KB
    cudaFuncSetAttribute(kA_attn, cudaFuncAttributeMaxDynamicSharedMemorySize, smem_kA);
    kA_attn<<<B * NG, 256, smem_kA>>>(enc);

    kB_combine<<<B, 256>>>(out_attn);

    k56_gru<<<128, 64>>>(Wih, Whh, bih, bhh, out_h);

    int smem_k7 = (32768 + 2 * WBUF7) * (int)sizeof(float);          // 198656 B
    cudaFuncSetAttribute(k7_logits, cudaFuncAttributeMaxDynamicSharedMemorySize, smem_k7);
    k7_logits<<<NB7, 512, smem_k7>>>(outW, outb);

    k8w_write<<<(B * V / 4) / 256, 256>>>(dout);
}

// round 12
// speedup vs baseline: 1.4615x; 1.3405x over previous
#include <cuda_runtime.h>
#include <math.h>

// Problem dims
#define H   256
#define H2  512
#define B   64
#define L   2048
#define V   32000
#define NG  4               // kA: groups per b
#define NCHG 16             // kA: chunks per group (32 l each)
#define NB7 125             // k7 blocks (V/256)
#define VT7 256
#define WP7 33
#define WBUF7 8448          // 256*33

typedef unsigned long long ull;

// ---------------- scratch (device globals) ----------------------------------------
__device__ __align__(16) float g_w2p[8][H2];
__device__ __align__(16) float g_w2[H2];
__device__ float g_bias;
__device__ __align__(16) float g_ehb[B];
__device__ __align__(16) float g_attn[B * L];        // raw energies
__device__ __align__(16) float g_pm[B * NG];
__device__ __align__(16) float g_ps[B * NG];
__device__ __align__(16) float g_ctxp[B * NG * H];
__device__ __align__(16) float g_xT[H2 * B];         // [emb; ctx] transposed [k][b]
__device__ __align__(16) float g_hT[H * B];          // hidden transposed [k][b]
__device__ __align__(16) float g_yT[H2 * B];         // [h_new; ctx] transposed [k][b]
__device__ __align__(16) float g_logits[B * V];
__device__ __align__(16) float g_lpm[B * 128];
__device__ __align__(16) float g_lps[B * 128];
__device__ __align__(16) float g_lse[B];
__device__ int g_cnt0;
__device__ int g_cntA[B];
__device__ int g_cnt7;

__device__ __forceinline__ ull fma2(ull a, ull x, ull c) {
    asm("fma.rn.f32x2 %0, %1, %2, %3;" : "=l"(a) : "l"(x), "l"(c), "l"(a));
    return a;
}
__device__ __forceinline__ ull pack2(float w) {
    ull r;
    asm("mov.b64 %0, {%1, %1};" : "=l"(r) : "f"(w));
    return r;
}
__device__ __forceinline__ float lo32(ull a) { return __uint_as_float((unsigned)(a & 0xffffffffull)); }
__device__ __forceinline__ float hi32(ull a) { return __uint_as_float((unsigned)(a >> 32)); }
__device__ __forceinline__ void cpasync16(unsigned smem, const void* g) {
    asm volatile("cp.async.ca.shared.global [%0], [%1], 16;" :: "r"(smem), "l"(g));
}
__device__ __forceinline__ void cpasync4(unsigned smem, const void* g) {
    asm volatile("cp.async.ca.shared.global [%0], [%1], 4;" :: "r"(smem), "l"(g));
}
#define CP_COMMIT() asm volatile("cp.async.commit_group;")
#define CP_WAIT0()  asm volatile("cp.async.wait_group 0;")
#define CP_WAIT1()  asm volatile("cp.async.wait_group 1;")

// ---------------- K0: w2 partials + bias + transposes + last-block combine --------
__global__ void k0_prep(const float* __restrict__ attn_W,
                        const float* __restrict__ attn_b,
                        const float* __restrict__ flatten,
                        const float* __restrict__ hidden,
                        const int*   __restrict__ input,
                        const float* __restrict__ emb_table)
{
    __shared__ float s_f[32];
    __shared__ float red[512];
    __shared__ float s_wh[H];
    __shared__ int s_last;
    int blk = blockIdx.x, tid = threadIdx.x;    // 512 threads, 9 blocks

    if (blk < 8) {
        if (tid < 32) s_f[tid] = flatten[blk * 32 + tid];
        __syncthreads();
        float acc = 0.f;
        #pragma unroll 8
        for (int i = 0; i < 32; i++)
            acc += attn_W[(size_t)(blk * 32 + i) * H2 + tid] * s_f[i];
        g_w2p[blk][tid] = acc;
    } else {
        red[tid] = (tid < H) ? flatten[tid] * attn_b[tid] : 0.f;
        __syncthreads();
        for (int s = 256; s > 0; s >>= 1) {
            if (tid < s) red[tid] += red[tid + s];
            __syncthreads();
        }
        if (tid == 0) g_bias = red[0];
        if (tid == 1) g_cnt7 = 0;
        if (tid >= 64 && tid < 128) g_cntA[tid - 64] = 0;
        for (int idx = tid; idx < B * H; idx += 512) {
            int b = idx >> 8, j = idx & 255;
            g_xT[j * B + b] = emb_table[(size_t)input[b] * H + j];
            g_hT[j * B + b] = hidden[idx];
        }
    }

    __threadfence();
    __syncthreads();
    if (tid == 0) s_last = (atomicAdd(&g_cnt0, 1) == 8) ? 1 : 0;
    __syncthreads();
    if (!s_last) return;

    float w = 0.f;
    #pragma unroll
    for (int k = 0; k < 8; k++) w += g_w2p[k][tid];
    g_w2[tid] = w;
    if (tid < H) s_wh[tid] = w;
    __syncthreads();

    int wid = tid >> 5, lane = tid & 31;        // 16 warps x 4 b
    float bias = g_bias;
    #pragma unroll
    for (int i = 0; i < 4; i++) {
        int b = wid * 4 + i;
        float a = 0.f;
        #pragma unroll
        for (int c = 0; c < 8; c++) {
            int k = c * 32 + lane;
            a += hidden[b * H + k] * s_wh[k];
        }
        #pragma unroll
        for (int o = 16; o > 0; o >>= 1) a += __shfl_down_sync(0xffffffffu, a, o);
        if (lane == 0) g_ehb[b] = a + bias;
    }
    if (tid == 0) g_cnt0 = 0;                   // reset for graph replay
}

// ---------------- KA: pipelined energies + online-softmax ctx + fused combine -----
// 256 blocks (b x 4 groups), 16 chunks of 32 l each, double-buffered cp.async.
// Last block per b combines the 4 group partials (ctx -> xT/yT, attn weights).
__global__ __launch_bounds__(256) void kA_attn(const float* __restrict__ enc,
                                               float* __restrict__ out_attn)
{
    extern __shared__ float sm[];
    // [0:16384)   two 32x256 tiles
    float* s_w2 = sm + 16384;        // 256
    float* s_e  = s_w2 + H;          // 32
    float* s_w  = s_e + 32;          // 32
    float* s_st = s_w + 32;          // [0]=m_run [1]=s_run [2]=m_new [3]=sc_old
                                     // [4..7]=combine scales [8]=mg [9]=inv
    int*   s_fl = (int*)(s_st + 12);

    int b = blockIdx.x >> 2;
    int g = blockIdx.x & 3;
    int tid = threadIdx.x;
    int wid = tid >> 5, lane = tid & 31;

    unsigned tb = (unsigned)__cvta_generic_to_shared(sm);
    const float4* src0 = (const float4*)(enc + (size_t)b * H);   // + l*B*H

    // prologue: chunk 0 into buf 0
    {
        int l0 = (g * NCHG) * 32;
        #pragma unroll
        for (int i = 0; i < 8; i++) {
            int idx = tid + 256 * i;
            int row = idx >> 6, col = idx & 63;
            cpasync16(tb + (unsigned)idx * 16, src0 + (size_t)(l0 + row) * 4096 + col);
        }
        CP_COMMIT();
    }
    s_w2[tid] = g_w2[H + tid];
    if (tid == 0) { s_st[0] = -INFINITY; s_st[1] = 0.f; }
    float ehb = g_ehb[b];
    float ctx_acc = 0.f;

    for (int i = 0; i < NCHG; i++) {
        if (i < NCHG - 1) {
            int l0 = (g * NCHG + i + 1) * 32;
            unsigned dst = tb + (unsigned)(((i + 1) & 1) * 8192) * 4;
            #pragma unroll
            for (int t = 0; t < 8; t++) {
                int idx = tid + 256 * t;
                int row = idx >> 6, col = idx & 63;
                cpasync16(dst + (unsigned)idx * 16, src0 + (size_t)(l0 + row) * 4096 + col);
            }
            CP_COMMIT();
            CP_WAIT1();
        } else {
            CP_WAIT0();
        }
        __syncthreads();

        float* tile = sm + (i & 1) * 8192;
        int l0 = (g * NCHG + i) * 32;

        // energies: 8 warps x 4 l
        #pragma unroll
        for (int r = 0; r < 4; r++) {
            int l = wid * 4 + r;
            const float4* tr = (const float4*)(tile + l * H);
            const float4* w4 = (const float4*)s_w2;
            float4 t0 = tr[lane],      w0 = w4[lane];
            float4 t1 = tr[32 + lane], w1 = w4[32 + lane];
            float a = t0.x * w0.x + t0.y * w0.y + t0.z * w0.z + t0.w * w0.w
                    + t1.x * w1.x + t1.y * w1.y + t1.z * w1.z + t1.w * w1.w;
            #pragma unroll
            for (int o = 16; o > 0; o >>= 1) a += __shfl_down_sync(0xffffffffu, a, o);
            if (lane == 0) {
                float e = a + ehb;
                s_e[l] = e;
                g_attn[b * L + l0 + l] = e;     // raw energy
            }
        }
        __syncthreads();

        // online max update
        if (wid == 0) {
            float m = s_e[lane];
            #pragma unroll
            for (int o = 16; o > 0; o >>= 1) m = fmaxf(m, __shfl_xor_sync(0xffffffffu, m, o));
            if (lane == 0) {
                float m_new = fmaxf(s_st[0], m);
                s_st[2] = m_new;
                s_st[3] = __expf(s_st[0] - m_new);
                s_st[0] = m_new;
            }
        }
        __syncthreads();
        float m_new = s_st[2], sc_old = s_st[3];
        if (tid < 32) s_w[tid] = __expf(s_e[tid] - m_new);
        __syncthreads();
        if (wid == 0) {
            float s = s_w[lane];
            #pragma unroll
            for (int o = 16; o > 0; o >>= 1) s += __shfl_xor_sync(0xffffffffu, s, o);
            if (lane == 0) s_st[1] = s_st[1] * sc_old + s;
        }

        // running context (thread = h)
        float a0 = 0.f, a1 = 0.f, a2 = 0.f, a3 = 0.f;
        #pragma unroll
        for (int l = 0; l < 32; l += 4) {
            a0 += s_w[l + 0] * tile[(l + 0) * H + tid];
            a1 += s_w[l + 1] * tile[(l + 1) * H + tid];
            a2 += s_w[l + 2] * tile[(l + 2) * H + tid];
            a3 += s_w[l + 3] * tile[(l + 3) * H + tid];
        }
        ctx_acc = ctx_acc * sc_old + ((a0 + a1) + (a2 + a3));
        // no trailing sync: next iter's top sync protects all shared state
    }

    g_ctxp[(size_t)(b * NG + g) * H + tid] = ctx_acc;
    if (tid == 0) { g_pm[b * NG + g] = s_st[0]; g_ps[b * NG + g] = s_st[1]; }

    // last-block-done combine for this b
    __threadfence();
    __syncthreads();
    if (tid == 0) s_fl[0] = (atomicAdd(&g_cntA[b], 1) == NG - 1) ? 1 : 0;
    __syncthreads();
    if (!s_fl[0]) return;

    if (tid == 0) {
        float m0 = g_pm[b * NG + 0], m1 = g_pm[b * NG + 1];
        float m2 = g_pm[b * NG + 2], m3 = g_pm[b * NG + 3];
        float m = fmaxf(fmaxf(m0, m1), fmaxf(m2, m3));
        float sc0 = __expf(m0 - m), sc1 = __expf(m1 - m);
        float sc2 = __expf(m2 - m), sc3 = __expf(m3 - m);
        float ssum = g_ps[b * NG + 0] * sc0 + g_ps[b * NG + 1] * sc1
                   + g_ps[b * NG + 2] * sc2 + g_ps[b * NG + 3] * sc3;
        s_st[4] = sc0; s_st[5] = sc1; s_st[6] = sc2; s_st[7] = sc3;
        s_st[8] = m; s_st[9] = 1.f / ssum;
    }
    __syncthreads();
    float mg = s_st[8], inv = s_st[9];

    float acc = s_st[4] * g_ctxp[(size_t)(b * NG + 0) * H + tid]
              + s_st[5] * g_ctxp[(size_t)(b * NG + 1) * H + tid]
              + s_st[6] * g_ctxp[(size_t)(b * NG + 2) * H + tid]
              + s_st[7] * g_ctxp[(size_t)(b * NG + 3) * H + tid];
    float ctxv = acc * inv;
    g_xT[(H + tid) * B + b] = ctxv;
    g_yT[(H + tid) * B + b] = ctxv;

    if (out_attn)
        for (int l = tid; l < L; l += 256)
            out_attn[b * L + l] = __expf(g_attn[b * L + l] - mg) * inv;
}

// ---------------- K56-v3: GRU, block per j, 8 warps split k, lanes = b-pairs ------
// Warps 0-3: Wih x slabs of 128 k; warps 4-7: Whh h slabs of 64 k.
// Partials reduced via smem; warp 0 computes gates. 256 blocks x 256 thr.
__global__ __launch_bounds__(256) void k56_gru(const float* __restrict__ Wih,
                                               const float* __restrict__ Whh,
                                               const float* __restrict__ bih,
                                               const float* __restrict__ bhh,
                                               float* __restrict__ out_h)
{
    __shared__ float s_px[8][3][64];            // warp, gate, b
    int j = blockIdx.x;                         // 0..255
    int tid = threadIdx.x;
    int wid = tid >> 5, lane = tid & 31;

    ull ar = 0, az = 0, an = 0;
    if (wid < 4) {
        int k0 = wid * 128;
        const float* wr = Wih + (size_t)j * H2 + k0;
        const float* wz = Wih + (size_t)(j + H) * H2 + k0;
        const float* wn = Wih + (size_t)(j + 2 * H) * H2 + k0;
        const float* xp = g_xT + k0 * B + lane * 2;
        #pragma unroll 8
        for (int k = 0; k < 128; k++) {
            ull x2 = *(const ull*)(xp + k * B);
            ar = fma2(ar, pack2(wr[k]), x2);
            az = fma2(az, pack2(wz[k]), x2);
            an = fma2(an, pack2(wn[k]), x2);
        }
    } else {
        int k0 = (wid - 4) * 64;
        const float* wr = Whh + (size_t)j * H + k0;
        const float* wz = Whh + (size_t)(j + H) * H + k0;
        const float* wn = Whh + (size_t)(j + 2 * H) * H + k0;
        const float* hp = g_hT + k0 * B + lane * 2;
        #pragma unroll 8
        for (int k = 0; k < 64; k++) {
            ull h2 = *(const ull*)(hp + k * B);
            ar = fma2(ar, pack2(wr[k]), h2);
            az = fma2(az, pack2(wz[k]), h2);
            an = fma2(an, pack2(wn[k]), h2);
        }
    }
    s_px[wid][0][lane * 2] = lo32(ar); s_px[wid][0][lane * 2 + 1] = hi32(ar);
    s_px[wid][1][lane * 2] = lo32(az); s_px[wid][1][lane * 2 + 1] = hi32(az);
    s_px[wid][2][lane * 2] = lo32(an); s_px[wid][2][lane * 2 + 1] = hi32(an);
    __syncthreads();

    if (wid != 0) return;
    float bir = bih[j], biz = bih[j + H], bin = bih[j + 2 * H];
    float bhr = bhh[j], bhz = bhh[j + H], bhn = bhh[j + 2 * H];
    float2 hp2 = *(const float2*)(g_hT + j * B + lane * 2);

    float hn_out[2];
    #pragma unroll
    for (int d = 0; d < 2; d++) {
        int bb = lane * 2 + d;
        float gir = s_px[0][0][bb] + s_px[1][0][bb] + s_px[2][0][bb] + s_px[3][0][bb] + bir;
        float giz = s_px[0][1][bb] + s_px[1][1][bb] + s_px[2][1][bb] + s_px[3][1][bb] + biz;
        float gin = s_px[0][2][bb] + s_px[1][2][bb] + s_px[2][2][bb] + s_px[3][2][bb] + bin;
        float ghr = s_px[4][0][bb] + s_px[5][0][bb] + s_px[6][0][bb] + s_px[7][0][bb] + bhr;
        float ghz = s_px[4][1][bb] + s_px[5][1][bb] + s_px[6][1][bb] + s_px[7][1][bb] + bhz;
        float ghn = s_px[4][2][bb] + s_px[5][2][bb] + s_px[6][2][bb] + s_px[7][2][bb] + bhn;
        float r = 1.f / (1.f + __expf(-(gir + ghr)));
        float z = 1.f / (1.f + __expf(-(giz + ghz)));
        float n = tanhf(gin + r * ghn);
        float hprev = d ? hp2.y : hp2.x;
        hn_out[d] = (1.f - z) * n + z * hprev;
    }
    *(float2*)(g_yT + j * B + lane * 2) = make_float2(hn_out[0], hn_out[1]);
    if (out_h) {
        out_h[(lane * 2 + 0) * H + j] = hn_out[0];
        out_h[(lane * 2 + 1) * H + j] = hn_out[1];
    }
}

// ---------------- K7: logits GEMM, y resident in smem, 512 threads ---------------
// 125 blocks x (256v x 64b), 16 warps/SM, thread tile 4v x 8b.
// W double-buffered (pitch 33, scalar broadcast reads), y loaded once (128KB).
#define SOP7 257
__global__ __launch_bounds__(512) void k7_logits(const float* __restrict__ outW,
                                                 const float* __restrict__ outb)
{
    extern __shared__ float sm[];
    float* s_y = sm;                             // 32768 floats (128KB)
    float* s_w = sm + 32768;                     // 2 x 8448 floats (~67.6KB)
    int tid = threadIdx.x;
    int v0b = blockIdx.x * VT7;

    unsigned syb = (unsigned)__cvta_generic_to_shared(s_y);
    unsigned swb = (unsigned)__cvta_generic_to_shared(s_w);

    // W chunk staging: 8192 scalars, 16/thread, 4-byte cp.async (alignment ok)
    #define K7_ISSUE_W(cc, buf) do {                                             \
        int _c = (cc), _bf = (buf);                                              \
        _Pragma("unroll")                                                        \
        for (int t = 0; t < 16; t++) {                                           \
            int idx = tid + 512 * t;                                             \
            int row = idx >> 5, k = idx & 31;                                    \
            cpasync4(swb + (unsigned)(_bf * WBUF7 + row * WP7 + k) * 4,          \
                     outW + (size_t)(v0b + row) * H2 + _c * 32 + k);             \
        }                                                                        \
    } while (0)

    // prologue: full y (8192 f4, 16/thread) + W chunk 0, one group
    #pragma unroll
    for (int t = 0; t < 16; t++) {
        int idx = tid + 512 * t;
        cpasync16(syb + (unsigned)idx * 16, g_yT + idx * 4);
    }
    K7_ISSUE_W(0, 0);
    CP_COMMIT();

    int bg = tid & 7;                            // 8 b-groups of 8
    int tv = tid >> 3;                           // 64 v-groups of 4
    int vl = tv * 4;
    int b0 = bg * 8;

    ull acc[4][4];
    #pragma unroll
    for (int i = 0; i < 4; i++)
        #pragma unroll
        for (int p = 0; p < 4; p++) acc[i][p] = 0ull;

    for (int c = 0; c < 16; c++) {
        if (c < 15) { K7_ISSUE_W(c + 1, (c + 1) & 1); CP_COMMIT(); CP_WAIT1(); }
        else        { CP_WAIT0(); }
        __syncthreads();

        const float* wb = s_w + (c & 1) * WBUF7;
        #pragma unroll 4
        for (int kk = 0; kk < 32; kk++) {
            int k = c * 32 + kk;
            ulonglong2 ya = *(const ulonglong2*)(s_y + k * 64 + b0);
            ulonglong2 yc = *(const ulonglong2*)(s_y + k * 64 + b0 + 4);
            #pragma unroll
            for (int i = 0; i < 4; i++) {
                ull w2 = pack2(wb[(vl + i) * WP7 + kk]);
                acc[i][0] = fma2(acc[i][0], w2, ya.x);
                acc[i][1] = fma2(acc[i][1], w2, ya.y);
                acc[i][2] = fma2(acc[i][2], w2, yc.x);
                acc[i][3] = fma2(acc[i][3], w2, yc.y);
            }
        }
    }
    __syncthreads();                             // all reads of s_y done

    // epilogue: stage 64b x 256v tile (pitch 257) in s_y region, add bias
    float* s_out = sm;
    #pragma unroll
    for (int i = 0; i < 4; i++) {
        float bb = outb[v0b + vl + i];
        #pragma unroll
        for (int p = 0; p < 4; p++) {
            s_out[(b0 + 2 * p + 0) * SOP7 + vl + i] = lo32(acc[i][p]) + bb;
            s_out[(b0 + 2 * p + 1) * SOP7 + vl + i] = hi32(acc[i][p]) + bb;
        }
    }
    __syncthreads();

    // coalesced float4 copy: 4096 f4, 8/thread
    #pragma unroll
    for (int t = 0; t < 8; t++) {
        int i = tid + 512 * t;
        int v4 = i & 63, b = i >> 6;
        const float* s = s_out + b * SOP7 + v4 * 4;
        *(float4*)(g_logits + (size_t)b * V + v0b + v4 * 4)
            = make_float4(s[0], s[1], s[2], s[3]);
    }

    // lse partials: 8 threads per b, 32 v each
    int bq = tid >> 3, i8 = tid & 7;
    {
        const float* rr = s_out + bq * SOP7 + i8 * 32;
        float m = -INFINITY;
        #pragma unroll
        for (int j = 0; j < 32; j++) m = fmaxf(m, rr[j]);
        #pragma unroll
        for (int o = 4; o > 0; o >>= 1) m = fmaxf(m, __shfl_xor_sync(0xffffffffu, m, o));
        float s = 0.f;
        #pragma unroll
        for (int j = 0; j < 32; j++) s += __expf(rr[j] - m);
        #pragma unroll
        for (int o = 4; o > 0; o >>= 1) s += __shfl_xor_sync(0xffffffffu, s, o);
        if (i8 == 0) {
            g_lpm[bq * 128 + blockIdx.x] = m;
            g_lps[bq * 128 + blockIdx.x] = s;
        }
    }

    // last block merges lse
    __shared__ int s_last;
    __threadfence();
    __syncthreads();
    if (tid == 0) s_last = (atomicAdd(&g_cnt7, 1) == NB7 - 1) ? 1 : 0;
    __syncthreads();
    if (!s_last) return;

    float m = -INFINITY;
    for (int i = i8; i < NB7; i += 8) m = fmaxf(m, g_lpm[bq * 128 + i]);
    #pragma unroll
    for (int o = 4; o > 0; o >>= 1) m = fmaxf(m, __shfl_xor_sync(0xffffffffu, m, o));
    float s = 0.f;
    for (int i = i8; i < NB7; i += 8)
        s += g_lps[bq * 128 + i] * __expf(g_lpm[bq * 128 + i] - m);
    #pragma unroll
    for (int o = 4; o > 0; o >>= 1) s += __shfl_xor_sync(0xffffffffu, s, o);
    if (i8 == 0) g_lse[bq] = m + logf(s);
}

// ---------------- K8w: out = logits - lse[b] ---------------------------------------
__global__ void k8w_write(float* __restrict__ out)
{
    int idx = blockIdx.x * 256 + threadIdx.x;   // float4 index
    int b = idx / (V / 4);
    float lse = g_lse[b];
    float4 v = ((const float4*)g_logits)[idx];
    v.x -= lse; v.y -= lse; v.z -= lse; v.w -= lse;
    ((float4*)out)[idx] = v;
}

// ---------------- host launch ------------------------------------------------------
extern "C" void kernel_launch(void* const* d_in, const int* in_sizes, int n_in,
                              void* d_out, int out_size)
{
    int s = (n_in >= 14 && in_sizes[3] == 1) ? 0 : -1;
    const int*   input    = (const int*)  d_in[0];
    const float* hidden   = (const float*)d_in[1];
    const float* enc      = (const float*)d_in[2];
    const float* emb      = (const float*)d_in[4 + s];
    const float* attn_W   = (const float*)d_in[5 + s];
    const float* attn_b   = (const float*)d_in[6 + s];
    const float* flatten  = (const float*)d_in[7 + s];
    const float* Wih      = (const float*)d_in[8 + s];
    const float* Whh      = (const float*)d_in[9 + s];
    const float* bih      = (const float*)d_in[10 + s];
    const float* bhh      = (const float*)d_in[11 + s];
    const float* outW     = (const float*)d_in[12 + s];
    const float* outb     = (const float*)d_in[13 + s];

    float* dout     = (float*)d_out;
    float* out_h    = (out_size >= B * V + B * H) ? dout + B * V : nullptr;
    float* out_attn = (out_size >= B * V + B * H + B * L) ? dout + B * V + B * H : nullptr;

    k0_prep<<<9, 512>>>(attn_W, attn_b, flatten, hidden, input, emb);

    int smem_kA = (16384 + 256 + 32 + 32 + 16) * (int)sizeof(float);  // ~66.9KB
    cudaFuncSetAttribute(kA_attn, cudaFuncAttributeMaxDynamicSharedMemorySize, smem_kA);
    kA_attn<<<B * NG, 256, smem_kA>>>(enc, out_attn);

    k56_gru<<<256, 256>>>(Wih, Whh, bih, bhh, out_h);

    int smem_k7 = (32768 + 2 * WBUF7) * (int)sizeof(float);          // 198656 B
    cudaFuncSetAttribute(k7_logits, cudaFuncAttributeMaxDynamicSharedMemorySize, smem_k7);
    k7_logits<<<NB7, 512, smem_k7>>>(outW, outb);

    k8w_write<<<(B * V / 4) / 256, 256>>>(dout);
}